// round 12
// baseline (speedup 1.0000x reference)
#include <cuda_runtime.h>
#include <cuda_bf16.h>

#define NUM_CLASSES 601
#define OUT_DIM 27
#define PAD_DIM 32          // pad table rows to 32 floats = 128 B = one L1 line
#define CHUNK 96            // rows per warp: 3 packed indices per shfl word
#define WARPS_PER_CTA 8

// Precomputed softmax table: 601 rows x 32 floats (cols 27..31 = 0 padding).
// 601*32*4 = 76,928 B -> L1/L2 resident.
__device__ __align__(128) float g_table[NUM_CLASSES * PAD_DIM];

// ---------------------------------------------------------------------------
// Kernel A: build softmax table. One warp per class row.
// Matches reference exactly: probs = exp(logits) / sum(exp(logits)).
// ---------------------------------------------------------------------------
__global__ void softmax_table_kernel(const float* __restrict__ W) {
    int r = blockIdx.x;          // 0..600
    int c = threadIdx.x;         // 0..31
    float e = 0.0f;
    if (c < OUT_DIM) {
        e = expf(W[r * OUT_DIM + c]);
    }
    float s = e;
    #pragma unroll
    for (int off = 16; off > 0; off >>= 1)
        s += __shfl_xor_sync(0xffffffffu, s, off);
    g_table[r * PAD_DIM + c] = (c < OUT_DIM) ? (e / s) : 0.0f;
}

// ---------------------------------------------------------------------------
// Kernel B: warp-cooperative gather, 96 rows per warp, SHFL amortized 3x.
// The kernel is LSU-issue-bound (~1.8 cyc per LDG/STG/SHFL per SM), so we
// cut instruction count per row:
//   - each lane loads 3 indices (rows j, j+32, j+64) and packs them into one
//     32-bit word (values < 601 fit in 10 bits)
//   - ONE shfl per iteration broadcasts 3 row indices; ALU extracts them
//   - per row: all lanes read ONE 128B table line (1 L1 wavefront, broadcast),
//     lanes 0..26 store the 27 output floats.
// LSU ops/row: 2.36 (vs 3.03 before); floor is 2.03 (gather + store).
// ---------------------------------------------------------------------------
__global__ void __launch_bounds__(256) gather_warp_kernel(
    const int* __restrict__ idx, float* __restrict__ out, int batch)
{
    const int lane = threadIdx.x & 31;
    const int warp = threadIdx.x >> 5;
    const long long base = ((long long)blockIdx.x * WARPS_PER_CTA + warp) * CHUNK;
    if (base >= batch) return;

    const long long nrows = batch - base;   // >= 1

    if (nrows >= CHUNK) {
        // fast path: full 96-row chunk
        int i0 = idx[base + lane];
        int i1 = idx[base + 32 + lane];
        int i2 = idx[base + 64 + lane];
        unsigned p = (unsigned)i0 | ((unsigned)i1 << 10) | ((unsigned)i2 << 20);

        float* o = out + base * OUT_DIM + lane;

        #pragma unroll 8
        for (int j = 0; j < 32; j++) {
            unsigned u = __shfl_sync(0xffffffffu, p, j);
            int r0 = (int)(u & 1023u);
            int r1 = (int)((u >> 10) & 1023u);
            int r2 = (int)(u >> 20);
            float v0 = g_table[r0 * PAD_DIM + lane];
            float v1 = g_table[r1 * PAD_DIM + lane];
            float v2 = g_table[r2 * PAD_DIM + lane];
            if (lane < OUT_DIM) {
                o[j * OUT_DIM]        = v0;
                o[(j + 32) * OUT_DIM] = v1;
                o[(j + 64) * OUT_DIM] = v2;
            }
        }
    } else {
        // tail chunk (only the last partial chunk lands here): 32 rows at a time
        for (long long b = base; b < batch; b += 32) {
            int mi = 0;
            if (b + lane < batch) mi = idx[b + lane];
            float* orow = out + b * OUT_DIM + lane;
            int n = (int)((batch - b) < 32 ? (batch - b) : 32);
            for (int j = 0; j < n; j++) {
                int rj = __shfl_sync(0xffffffffu, mi, j);
                float v = g_table[rj * PAD_DIM + lane];
                if (lane < OUT_DIM) orow[j * OUT_DIM] = v;
            }
        }
    }
}

extern "C" void kernel_launch(void* const* d_in, const int* in_sizes, int n_in,
                              void* d_out, int out_size) {
    const int* idx;
    const float* W;
    int batch;
    if (in_sizes[0] == NUM_CLASSES * OUT_DIM) {
        W = (const float*)d_in[0];
        idx = (const int*)d_in[1];
        batch = in_sizes[1];
    } else {
        idx = (const int*)d_in[0];
        W = (const float*)d_in[1];
        batch = in_sizes[0];
    }

    softmax_table_kernel<<<NUM_CLASSES, 32>>>(W);

    // 8 warps/block, 96 rows/warp -> 768 rows per block
    long long nblocks = ((long long)batch + (WARPS_PER_CTA * CHUNK - 1)) / (WARPS_PER_CTA * CHUNK);
    gather_warp_kernel<<<(int)nblocks, 256>>>(idx, (float*)d_out, batch);
}

// round 14
// speedup vs baseline: 1.7950x; 1.7950x over previous
#include <cuda_runtime.h>
#include <cuda_bf16.h>

#define NUM_CLASSES 601
#define OUT_DIM 27
#define PAD_DIM 32          // table rows padded to 32 floats = 128 B = one L1 line
#define CHUNK 32            // rows per warp; CHUNK*OUT_DIM = 864 floats = 3456 B (27 x 128B)
#define WARPS_PER_CTA 8

// Precomputed softmax table: 601 rows x 32 floats (cols 27..31 = 0 padding).
// 601*32*4 = 76,928 B -> L1/L2 resident.
__device__ __align__(128) float g_table[NUM_CLASSES * PAD_DIM];

// ---------------------------------------------------------------------------
// Kernel A: build softmax table. 8 warps/block, one warp per class row.
// Matches reference exactly: probs = exp(logits) / sum(exp(logits)).
// ---------------------------------------------------------------------------
__global__ void softmax_table_kernel(const float* __restrict__ W) {
    int r = blockIdx.x * 8 + (threadIdx.x >> 5);   // class row
    int c = threadIdx.x & 31;
    if (r >= NUM_CLASSES) return;
    float e = 0.0f;
    if (c < OUT_DIM) {
        e = expf(W[r * OUT_DIM + c]);
    }
    float s = e;
    #pragma unroll
    for (int off = 16; off > 0; off >>= 1)
        s += __shfl_xor_sync(0xffffffffu, s, off);
    g_table[r * PAD_DIM + c] = (c < OUT_DIM) ? (e / s) : 0.0f;
}

// ---------------------------------------------------------------------------
// Kernel B: warp-cooperative gather with FLAT 128B-ALIGNED stores.
// One warp per 32-row chunk (R7's proven grid shape). The chunk's 864 output
// floats are contiguous and 128B-aligned, so we loop over 27 flat groups of
// 32 elements:
//   lane k, group j -> flat element e = 32j + k
//     row-in-chunk = e / 27  (shfl source, per-lane)
//     col          = e % 27
//   1 shfl + 1 gather LDG (2-3 table lines) + 1 fully-coalesced aligned STG.
// vs R7: store wavefronts drop 59 -> 27, all 32 lanes active, fewer LSU ops.
// ---------------------------------------------------------------------------
__global__ void __launch_bounds__(256) gather_flat_kernel(
    const int* __restrict__ idx, float* __restrict__ out, int batch)
{
    const int lane = threadIdx.x & 31;
    const int warp = threadIdx.x >> 5;
    const long long base = ((long long)blockIdx.x * WARPS_PER_CTA + warp) * CHUNK;
    if (base >= batch) return;

    const long long nrows = batch - base;   // >= 1

    if (nrows >= CHUNK) {
        // fast path: full 32-row chunk
        int mi = idx[base + lane];
        float* o = out + base * OUT_DIM;    // 3456*k bytes -> 128B aligned

        #pragma unroll 9
        for (int j = 0; j < OUT_DIM; j++) {
            int e = 32 * j + lane;          // 0..863
            int row = e / 27;               // 0..31 (mul-shift)
            int col = e - row * 27;
            int r = __shfl_sync(0xffffffffu, mi, row);
            o[e] = g_table[r * PAD_DIM + col];
        }
    } else {
        // tail chunk: per-row broadcast gather (rarely taken)
        int mi = 0;
        if (base + lane < batch) mi = idx[base + lane];
        float* orow = out + base * OUT_DIM + lane;
        int n = (int)nrows;
        for (int j = 0; j < n; j++) {
            int rj = __shfl_sync(0xffffffffu, mi, j);
            float v = g_table[rj * PAD_DIM + lane];
            if (lane < OUT_DIM) orow[j * OUT_DIM] = v;
        }
    }
}

extern "C" void kernel_launch(void* const* d_in, const int* in_sizes, int n_in,
                              void* d_out, int out_size) {
    const int* idx;
    const float* W;
    int batch;
    if (in_sizes[0] == NUM_CLASSES * OUT_DIM) {
        W = (const float*)d_in[0];
        idx = (const int*)d_in[1];
        batch = in_sizes[1];
    } else {
        idx = (const int*)d_in[0];
        W = (const float*)d_in[1];
        batch = in_sizes[0];
    }

    softmax_table_kernel<<<(NUM_CLASSES + 7) / 8, 256>>>(W);

    // 8 warps/block, 32 rows/warp -> 256 rows per block (R7 grid shape)
    long long nblocks = ((long long)batch + (WARPS_PER_CTA * CHUNK - 1)) / (WARPS_PER_CTA * CHUNK);
    gather_flat_kernel<<<(int)nblocks, 256>>>(idx, (float*)d_out, batch);
}